// round 3
// baseline (speedup 1.0000x reference)
#include <cuda_runtime.h>
#include <cuda_bf16.h>

// Problem constants (fixed by the reference)
#define NROWS 8192
#define NCOLS 8192
#define RB 32
#define CB 32
#define HID 100
#define DIO (RB*CB)
#define ROW_SPLIT 4   // grid.z split of each (rb,cb) block for load balance

// Scratch (no cudaMalloc allowed)
__device__ float g_blk[RB*CB];        // block sums
__device__ int   g_rowb[RB+1];        // row boundaries (== row cumsum)
__device__ int   g_colb[CB+1];        // col boundaries (== col cumsum)

__device__ __forceinline__ int lower_bound_dev(const int* a, int n, int key) {
    int lo = 0, hi = n;
    while (lo < hi) {
        int m = (lo + hi) >> 1;
        if (a[m] < key) lo = m + 1; else hi = m;
    }
    return lo;
}

// ---------------------------------------------------------------------------
// K0: boundaries via binary search on sorted ids, zero the block-sum scratch,
//     and emit the cumsum outputs (boundaries ARE the cumsums for sorted ids).
// ---------------------------------------------------------------------------
__global__ void k_setup(const int* __restrict__ row_ids,
                        const int* __restrict__ col_ids,
                        float* __restrict__ out, int out_size) {
    int t = threadIdx.x;  // 256 threads
    if (t <= RB) {
        int v = lower_bound_dev(row_ids, NROWS, t);
        g_rowb[t] = v;
        if (out_size >= DIO + (RB+1) + (CB+1))
            out[DIO + t] = (float)v;
    } else if (t >= 64 && t <= 64 + CB) {
        int k = t - 64;
        int v = lower_bound_dev(col_ids, NCOLS, k);
        g_colb[k] = v;
        if (out_size >= DIO + (RB+1) + (CB+1))
            out[DIO + (RB+1) + k] = (float)v;
    }
    for (int i = t; i < RB*CB; i += blockDim.x) g_blk[i] = 0.0f;
}

// ---------------------------------------------------------------------------
// K1: streaming block-sum. One CTA per (cb, rb, row-split). Every element the
//     CTA touches belongs to ONE bin -> pure register accumulation, a single
//     shuffle-tree reduction, and ONE global atomicAdd per CTA.
//     Grid: (CB, RB, ROW_SPLIT), 256 threads (8 warps). Warp w of split s
//     handles rows rlo + s + 4*w, step 32 (interleaved -> balanced).
// ---------------------------------------------------------------------------
__global__ __launch_bounds__(256) void k_blocksum(const float* __restrict__ X) {
    const int cb = blockIdx.x, rb = blockIdx.y, s = blockIdx.z;
    const int rlo = g_rowb[rb], rhi = g_rowb[rb+1];
    const int clo = g_colb[cb], chi = g_colb[cb+1];
    const int warp = threadIdx.x >> 5, lane = threadIdx.x & 31;

    // 16B-aligned body [ca, ce), scalar head [clo, ca) and tail [ce, chi)
    int ca = (clo + 3) & ~3; if (ca > chi) ca = chi;
    int ce = chi & ~3;       if (ce < ca)  ce = ca;
    const int hN = ca - clo, tN = chi - ce;
    const int c4lo = ca >> 2, c4hi = ce >> 2;

    float a0 = 0.f, a1 = 0.f, a2 = 0.f, a3 = 0.f;

    for (int r = rlo + s + 4*warp; r < rhi; r += ROW_SPLIT * 8) {
        const float* row = X + (size_t)r * NCOLS;
        if (lane < hN) a0 += row[clo + lane];
        const float4* row4 = (const float4*)row;
        for (int c = c4lo + lane; c < c4hi; c += 32) {
            float4 v = row4[c];
            a0 += v.x; a1 += v.y; a2 += v.z; a3 += v.w;
        }
        if (lane < tN) a1 += row[ce + lane];
    }

    float acc = (a0 + a1) + (a2 + a3);
    #pragma unroll
    for (int o = 16; o; o >>= 1) acc += __shfl_xor_sync(0xFFFFFFFFu, acc, o);

    __shared__ float sred[8];
    if (lane == 0) sred[warp] = acc;
    __syncthreads();
    if (threadIdx.x == 0) {
        float tot = 0.f;
        #pragma unroll
        for (int w = 0; w < 8; w++) tot += sred[w];
        atomicAdd(&g_blk[rb * CB + cb], tot);   // -> REDG, 4096 total
    }
}

// ---------------------------------------------------------------------------
// K2: divide by counts, 3-layer MLP, sigmoid, write propensity to out[0:1024).
//     Single CTA, 1024 threads. Layer1 K-dim split 8 ways for latency hiding.
// ---------------------------------------------------------------------------
__global__ __launch_bounds__(1024) void k_mlp(const float* __restrict__ W1,
                                              const float* __restrict__ b1,
                                              const float* __restrict__ W2,
                                              const float* __restrict__ b2,
                                              const float* __restrict__ W3,
                                              const float* __restrict__ b3,
                                              float* __restrict__ out) {
    __shared__ float xs[DIO];
    __shared__ float h1p[800];
    __shared__ float h1[HID];
    __shared__ float h2[HID];
    const int t = threadIdx.x;

    // block mean
    {
        int rb = t >> 5, cbi = t & 31;
        float rc = (float)(g_rowb[rb+1] - g_rowb[rb]);
        float cc = (float)(g_colb[cbi+1] - g_colb[cbi]);
        float cnt = fmaxf(rc * cc, 1.0f);
        xs[t] = g_blk[t] / cnt;
    }
    __syncthreads();

    // layer 1: h1 = relu(x @ W1 + b1), x[1024], W1[1024,100]
    if (t < 800) {
        const int j = t % HID;        // output neuron
        const int sl = t / HID;       // K slice (8 slices of 128)
        const int i0 = sl * 128;
        float acc = 0.f;
        #pragma unroll 8
        for (int i = 0; i < 128; i++)
            acc += xs[i0 + i] * W1[(size_t)(i0 + i) * HID + j];
        h1p[t] = acc;
    }
    __syncthreads();
    if (t < HID) {
        float a = b1[t];
        #pragma unroll
        for (int sl = 0; sl < 8; sl++) a += h1p[sl * HID + t];
        h1[t] = fmaxf(a, 0.f);
    }
    __syncthreads();

    // layer 2: h2 = relu(h1 @ W2 + b2), W2[100,100]
    if (t < HID) {
        float a = b2[t];
        #pragma unroll 4
        for (int i = 0; i < HID; i++) a += h1[i] * W2[i * HID + t];
        h2[t] = fmaxf(a, 0.f);
    }
    __syncthreads();

    // layer 3: out = sigmoid(h2 @ W3 + b3), W3[100,1024]
    {
        float a = b3[t];
        #pragma unroll 4
        for (int i = 0; i < HID; i++) a += h2[i] * W3[(size_t)i * DIO + t];
        out[t] = 1.0f / (1.0f + __expf(-a));
    }
}

extern "C" void kernel_launch(void* const* d_in, const int* in_sizes, int n_in,
                              void* d_out, int out_size) {
    const float* X       = (const float*)d_in[0];
    const int*   row_ids = (const int*)  d_in[1];
    const int*   col_ids = (const int*)  d_in[2];
    const float* W1      = (const float*)d_in[3];
    const float* b1      = (const float*)d_in[4];
    const float* W2      = (const float*)d_in[5];
    const float* b2      = (const float*)d_in[6];
    const float* W3      = (const float*)d_in[7];
    const float* b3      = (const float*)d_in[8];
    float* out = (float*)d_out;

    k_setup<<<1, 256>>>(row_ids, col_ids, out, out_size);
    k_blocksum<<<dim3(CB, RB, ROW_SPLIT), 256>>>(X);
    k_mlp<<<1, 1024>>>(W1, b1, W2, b2, W3, b3, out);
}

// round 4
// speedup vs baseline: 1.2752x; 1.2752x over previous
#include <cuda_runtime.h>
#include <cuda_bf16.h>

// Problem constants (fixed by the reference)
#define NROWS 8192
#define NCOLS 8192
#define RB 32
#define CB 32
#define HID 100
#define DIO (RB*CB)
#define ROW_SPLIT 8             // grid.z split of each (rb,cb) block
#define W_STEP (ROW_SPLIT*8)    // 64 row-slots per (rb,cb): 8 warps x 8 splits

// Scratch (no cudaMalloc allowed)
__device__ float g_blk[RB*CB];        // block sums
__device__ int   g_rowb[RB+1];        // row boundaries (== row cumsum)
__device__ int   g_colb[CB+1];        // col boundaries (== col cumsum)

// ---------------------------------------------------------------------------
// K0: boundaries via one coalesced pass over the sorted ids (adjacent diff),
//     zero the block-sum scratch, emit cumsum outputs.
//     Block 0 -> row_ids (+ zero g_blk), block 1 -> col_ids. 1024 threads.
// ---------------------------------------------------------------------------
__global__ __launch_bounds__(1024) void k_setup(const int* __restrict__ row_ids,
                                                const int* __restrict__ col_ids,
                                                float* __restrict__ out) {
    const bool rowpass = (blockIdx.x == 0);
    const int  nb  = rowpass ? RB : CB;
    const int  n   = rowpass ? NROWS : NCOLS;
    const int* ids = rowpass ? row_ids : col_ids;
    int*  bnd = rowpass ? g_rowb : g_colb;
    float* o  = out + DIO + (rowpass ? 0 : (RB + 1));

    for (int i = threadIdx.x; i < n; i += blockDim.x) {
        int cur  = ids[i];
        int prev = (i == 0) ? -1 : ids[i - 1];
        for (int k = prev + 1; k <= cur; k++) { bnd[k] = i; o[k] = (float)i; }
        if (i == n - 1)
            for (int k = cur + 1; k <= nb; k++) { bnd[k] = n; o[k] = (float)n; }
    }
    if (rowpass)
        for (int i = threadIdx.x; i < DIO; i += blockDim.x) g_blk[i] = 0.0f;
}

// ---------------------------------------------------------------------------
// K1: streaming block-sum. CTA = (cb, rb, split); 256 threads / 8 warps.
//     Each warp owns row-slot w = warp*ROW_SPLIT + split, rows rlo+w+k*64.
//     4-row unrolling: each c-iteration issues 4 independent LDG.128 before
//     any dependent FADD -> MLP >= 4 per warp (vs 1 before).
//     One shuffle-tree + one global atomicAdd per CTA.
// ---------------------------------------------------------------------------
__global__ __launch_bounds__(256) void k_blocksum(const float* __restrict__ X) {
    const int cb = blockIdx.x, rb = blockIdx.y, s = blockIdx.z;
    const int rlo = g_rowb[rb], rhi = g_rowb[rb + 1];
    const int clo = g_colb[cb], chi = g_colb[cb + 1];
    const int warp = threadIdx.x >> 5, lane = threadIdx.x & 31;

    // 16B-aligned body [ca, ce), scalar head [clo, ca) and tail [ce, chi)
    int ca = (clo + 3) & ~3; if (ca > chi) ca = chi;
    int ce = chi & ~3;       if (ce < ca)  ce = ca;
    const int hN = ca - clo, tN = chi - ce;
    const int c4lo = ca >> 2, c4hi = ce >> 2;

    float a0 = 0.f, a1 = 0.f, a2 = 0.f, a3 = 0.f;

    int r = rlo + warp * ROW_SPLIT + s;

    // 4-row unrolled groups (rows strided by W_STEP=64, fully independent)
    for (; r + 3 * W_STEP < rhi; r += 4 * W_STEP) {
        const float* q0 = X + (size_t)r * NCOLS;
        const float* q1 = X + (size_t)(r +     W_STEP) * NCOLS;
        const float* q2 = X + (size_t)(r + 2 * W_STEP) * NCOLS;
        const float* q3 = X + (size_t)(r + 3 * W_STEP) * NCOLS;
        if (lane < hN) {
            a0 += q0[clo + lane]; a1 += q1[clo + lane];
            a2 += q2[clo + lane]; a3 += q3[clo + lane];
        }
        const float4* p0 = (const float4*)q0;
        const float4* p1 = (const float4*)q1;
        const float4* p2 = (const float4*)q2;
        const float4* p3 = (const float4*)q3;
        for (int c = c4lo + lane; c < c4hi; c += 32) {
            float4 v0 = p0[c];
            float4 v1 = p1[c];
            float4 v2 = p2[c];
            float4 v3 = p3[c];
            a0 += (v0.x + v0.y) + (v0.z + v0.w);
            a1 += (v1.x + v1.y) + (v1.z + v1.w);
            a2 += (v2.x + v2.y) + (v2.z + v2.w);
            a3 += (v3.x + v3.y) + (v3.z + v3.w);
        }
        if (lane < tN) {
            a0 += q0[ce + lane]; a1 += q1[ce + lane];
            a2 += q2[ce + lane]; a3 += q3[ce + lane];
        }
    }
    // leftover rows, one at a time
    for (; r < rhi; r += W_STEP) {
        const float* q0 = X + (size_t)r * NCOLS;
        if (lane < hN) a0 += q0[clo + lane];
        const float4* p0 = (const float4*)q0;
        for (int c = c4lo + lane; c < c4hi; c += 32) {
            float4 v0 = p0[c];
            a0 += (v0.x + v0.y) + (v0.z + v0.w);
        }
        if (lane < tN) a0 += q0[ce + lane];
    }

    float acc = (a0 + a1) + (a2 + a3);
    #pragma unroll
    for (int o = 16; o; o >>= 1) acc += __shfl_xor_sync(0xFFFFFFFFu, acc, o);

    __shared__ float sred[8];
    if (lane == 0) sred[warp] = acc;
    __syncthreads();
    if (threadIdx.x == 0) {
        float tot = 0.f;
        #pragma unroll
        for (int w = 0; w < 8; w++) tot += sred[w];
        atomicAdd(&g_blk[rb * CB + cb], tot);   // -> REDG, 8192 total
    }
}

// ---------------------------------------------------------------------------
// K2: divide by counts, 3-layer MLP, sigmoid, write propensity to out[0:1024).
//     Single CTA, 1024 threads. High-MLP loads: layer1 8-way K-split with
//     unroll 16, layer2 10-way K-split (10 loads fully in flight),
//     layer3 unroll 20.
// ---------------------------------------------------------------------------
__global__ __launch_bounds__(1024) void k_mlp(const float* __restrict__ W1,
                                              const float* __restrict__ b1,
                                              const float* __restrict__ W2,
                                              const float* __restrict__ b2,
                                              const float* __restrict__ W3,
                                              const float* __restrict__ b3,
                                              float* __restrict__ out) {
    __shared__ float xs[DIO];
    __shared__ float h1p[800];
    __shared__ float h2p[1000];
    __shared__ float h1[HID];
    __shared__ float h2[HID];
    const int t = threadIdx.x;

    // block mean
    {
        int rb = t >> 5, cbi = t & 31;
        float rc = (float)(g_rowb[rb + 1] - g_rowb[rb]);
        float cc = (float)(g_colb[cbi + 1] - g_colb[cbi]);
        float cnt = fmaxf(rc * cc, 1.0f);
        xs[t] = g_blk[t] / cnt;
    }
    __syncthreads();

    // layer 1: h1 = relu(x @ W1 + b1), x[1024], W1[1024,100]; 8 K-slices x 100
    if (t < 800) {
        const int j  = t % HID;
        const int i0 = (t / HID) * 128;
        float acc = 0.f;
        #pragma unroll 16
        for (int i = 0; i < 128; i++)
            acc += xs[i0 + i] * W1[(size_t)(i0 + i) * HID + j];
        h1p[t] = acc;
    }
    __syncthreads();
    if (t < HID) {
        float a = b1[t];
        #pragma unroll
        for (int sl = 0; sl < 8; sl++) a += h1p[sl * HID + t];
        h1[t] = fmaxf(a, 0.f);
    }
    __syncthreads();

    // layer 2: h2 = relu(h1 @ W2 + b2), W2[100,100]; 10 K-slices x 100
    if (t < 1000) {
        const int j  = t % HID;
        const int i0 = (t / HID) * 10;
        float acc = 0.f;
        #pragma unroll
        for (int i = 0; i < 10; i++)
            acc += h1[i0 + i] * W2[(i0 + i) * HID + j];
        h2p[t] = acc;
    }
    __syncthreads();
    if (t < HID) {
        float a = b2[t];
        #pragma unroll
        for (int sl = 0; sl < 10; sl++) a += h2p[sl * HID + t];
        h2[t] = fmaxf(a, 0.f);
    }
    __syncthreads();

    // layer 3: out = sigmoid(h2 @ W3 + b3), W3[100,1024]
    {
        float a = b3[t];
        #pragma unroll 20
        for (int i = 0; i < HID; i++) a += h2[i] * W3[(size_t)i * DIO + t];
        out[t] = 1.0f / (1.0f + __expf(-a));
    }
}

extern "C" void kernel_launch(void* const* d_in, const int* in_sizes, int n_in,
                              void* d_out, int out_size) {
    const float* X       = (const float*)d_in[0];
    const int*   row_ids = (const int*)  d_in[1];
    const int*   col_ids = (const int*)  d_in[2];
    const float* W1      = (const float*)d_in[3];
    const float* b1      = (const float*)d_in[4];
    const float* W2      = (const float*)d_in[5];
    const float* b2      = (const float*)d_in[6];
    const float* W3      = (const float*)d_in[7];
    const float* b3      = (const float*)d_in[8];
    float* out = (float*)d_out;

    k_setup<<<2, 1024>>>(row_ids, col_ids, out);
    k_blocksum<<<dim3(CB, RB, ROW_SPLIT), 256>>>(X);
    k_mlp<<<1, 1024>>>(W1, b1, W2, b2, W3, b3, out);
}